// round 3
// baseline (speedup 1.0000x reference)
#include <cuda_runtime.h>

// ---------------- problem constants ----------------
#define HW   196
#define BB   8
#define SEQ  32
#define DD   768
#define DH   192
#define HALF 96                  // DH/2
#define NSEQ (BB*HW)             // 1568
#define MTOT (NSEQ*SEQ)          // 50176

// ---------------- scratch (__device__ globals) ------------------------------
__device__ float g_xd [MTOT*DH];
__device__ float g_q  [MTOT*DH];
__device__ float g_k  [MTOT*DH];
__device__ float g_v  [MTOT*DH];
__device__ float g_ret[MTOT*DH];

// xPos tables: [t (0..31)][p (0..95)]
__device__ float g_cos_u[SEQ*HALF];
__device__ float g_sin_u[SEQ*HALF];
__device__ float g_cos_d[SEQ*HALF];
__device__ float g_sin_d[SEQ*HALF];

// row m of the logical xr[(b*hw), s, D] maps to this row of x[(hw), b*s, D]
__device__ __forceinline__ int x_row_of(int m) {
    int q  = m >> 5;
    int t  = m & 31;
    int bi = q / HW;
    int hi = q - bi * HW;
    return hi * (BB * SEQ) + bi * SEQ + t;
}

// ---------------- xPos table precompute (fp64) ------------------------------
__global__ void k_tables() {
    int i = blockIdx.x * blockDim.x + threadIdx.x;
    if (i >= SEQ * HALF) return;
    int t = i / HALF, p = i % HALF;
    double base = (2.0 * p + 0.4 * (double)DH) / (1.4 * (double)DH);
    double sc_u = pow(base, (double)t / 512.0);
    double sc_d = 1.0 / sc_u;
    double invf = pow(10000.0, -(double)p / (double)HALF);
    double ang  = (double)t * invf;
    double s = sin(ang), c = cos(ang);
    g_cos_u[i] = (float)(c * sc_u);
    g_sin_u[i] = (float)(s * sc_u);
    g_cos_d[i] = (float)(c * sc_d);
    g_sin_d[i] = (float)(s * sc_d);
}

// ---------------- tiled SGEMM: C(MxN) = A(MxK) @ B(KxN) ---------------------
// BM=128, BK=16, microtile 8x8, double-buffered smem.
// MODE 0: A gathered from x, +bias           -> C
// MODE 1: xPos upscale epilogue              -> C
// MODE 2: xPos downscale epilogue            -> C
// MODE 3: plain                              -> C
// MODE 4: +bias +x residual (gathered), gathered store -> C
template <int MODE, int BN>
__global__ void __launch_bounds__((BN/8)*16) k_gemm(
    const float* __restrict__ A, const float* __restrict__ B,
    const float* __restrict__ bias, const float* __restrict__ xres,
    float* __restrict__ C, int K, int N)
{
    constexpr int BM = 128, BK = 16;
    constexpr int THREADS  = (BN / 8) * 16;
    constexpr int AMP      = 132;                       // padded BM (16B-aligned rows, fewer store conflicts)
    constexpr int A_F4_PER = (BM * BK / 4) / THREADS;   // 4 (BN=64) or 2 (BN=128)
    constexpr int B_F4_PER = (BK * BN / 4) / THREADS;   // 2

    __shared__ __align__(16) float As[2][BK][AMP];
    __shared__ __align__(16) float Bs[2][BK][BN];

    const int tid = threadIdx.x;
    const int txx = tid % (BN / 8);
    const int tyy = tid / (BN / 8);
    const int bm  = blockIdx.y * BM;
    const int bn  = blockIdx.x * BN;

    // precompute gathered A row pointers for this thread's load slots
    int aRow[A_F4_PER], aKq[A_F4_PER];
    const float* aPtr[A_F4_PER];
#pragma unroll
    for (int i = 0; i < A_F4_PER; i++) {
        int f4 = tid + i * THREADS;
        aRow[i] = f4 >> 2;
        aKq[i]  = f4 & 3;
        int gm  = bm + aRow[i];
        int gr  = (MODE == 0) ? x_row_of(gm) : gm;
        aPtr[i] = A + (size_t)gr * K + aKq[i] * 4;
    }
    int bRow[B_F4_PER], bCol[B_F4_PER];
#pragma unroll
    for (int i = 0; i < B_F4_PER; i++) {
        int f4 = tid + i * THREADS;
        bRow[i] = f4 / (BN / 4);
        bCol[i] = (f4 % (BN / 4)) * 4;
    }

    float acc[8][8];
#pragma unroll
    for (int r = 0; r < 8; r++)
#pragma unroll
        for (int c = 0; c < 8; c++) acc[r][c] = 0.0f;

    float4 aReg[A_F4_PER], bReg[B_F4_PER];

    auto loadG = [&](int k0) {
#pragma unroll
        for (int i = 0; i < A_F4_PER; i++)
            aReg[i] = *(const float4*)(aPtr[i] + k0);
#pragma unroll
        for (int i = 0; i < B_F4_PER; i++)
            bReg[i] = *(const float4*)(B + (size_t)(k0 + bRow[i]) * N + bn + bCol[i]);
    };
    auto storeS = [&](int buf) {
#pragma unroll
        for (int i = 0; i < A_F4_PER; i++) {
            As[buf][aKq[i] * 4 + 0][aRow[i]] = aReg[i].x;
            As[buf][aKq[i] * 4 + 1][aRow[i]] = aReg[i].y;
            As[buf][aKq[i] * 4 + 2][aRow[i]] = aReg[i].z;
            As[buf][aKq[i] * 4 + 3][aRow[i]] = aReg[i].w;
        }
#pragma unroll
        for (int i = 0; i < B_F4_PER; i++)
            *(float4*)&Bs[buf][bRow[i]][bCol[i]] = bReg[i];
    };
    auto compute = [&](int buf) {
#pragma unroll
        for (int kk = 0; kk < BK; kk++) {
            float a[8], b[8];
            *(float4*)&a[0] = *(const float4*)&As[buf][kk][tyy * 8];
            *(float4*)&a[4] = *(const float4*)&As[buf][kk][tyy * 8 + 4];
            *(float4*)&b[0] = *(const float4*)&Bs[buf][kk][txx * 8];
            *(float4*)&b[4] = *(const float4*)&Bs[buf][kk][txx * 8 + 4];
#pragma unroll
            for (int r = 0; r < 8; r++)
#pragma unroll
                for (int c = 0; c < 8; c++) acc[r][c] += a[r] * b[c];
        }
    };

    loadG(0);
    storeS(0);
    __syncthreads();
    int cur = 0;
    for (int k0 = BK; k0 < K; k0 += BK) {
        loadG(k0);
        compute(cur);
        storeS(cur ^ 1);
        __syncthreads();
        cur ^= 1;
    }
    compute(cur);

    const int m0 = bm + tyy * 8;
    const int n0 = bn + txx * 8;

    if (MODE == 0) {
        float bv[8];
        *(float4*)&bv[0] = *(const float4*)(bias + n0);
        *(float4*)&bv[4] = *(const float4*)(bias + n0 + 4);
#pragma unroll
        for (int r = 0; r < 8; r++) {
            float o[8];
#pragma unroll
            for (int c = 0; c < 8; c++) o[c] = acc[r][c] + bv[c];
            *(float4*)(C + (size_t)(m0 + r) * N + n0)     = *(float4*)&o[0];
            *(float4*)(C + (size_t)(m0 + r) * N + n0 + 4) = *(float4*)&o[4];
        }
    } else if (MODE == 1 || MODE == 2) {
        const float* ct = (MODE == 1) ? g_cos_u : g_cos_d;
        const float* st = (MODE == 1) ? g_sin_u : g_sin_d;
        const int p0 = n0 >> 1;          // 8 cols = 4 (even,odd) pairs
#pragma unroll
        for (int r = 0; r < 8; r++) {
            int m = m0 + r;
            int t = m & 31;
            float o[8];
#pragma unroll
            for (int pp = 0; pp < 4; pp++) {
                float cc = ct[t * HALF + p0 + pp];
                float ss = st[t * HALF + p0 + pp];
                float e = acc[r][pp * 2], od = acc[r][pp * 2 + 1];
                o[pp * 2]     = e * cc - od * ss;
                o[pp * 2 + 1] = od * cc + e * ss;
            }
            *(float4*)(C + (size_t)m * N + n0)     = *(float4*)&o[0];
            *(float4*)(C + (size_t)m * N + n0 + 4) = *(float4*)&o[4];
        }
    } else if (MODE == 3) {
#pragma unroll
        for (int r = 0; r < 8; r++) {
            *(float4*)(C + (size_t)(m0 + r) * N + n0)     = *(float4*)&acc[r][0];
            *(float4*)(C + (size_t)(m0 + r) * N + n0 + 4) = *(float4*)&acc[r][4];
        }
    } else { // MODE 4
        float bv[8];
        *(float4*)&bv[0] = *(const float4*)(bias + n0);
        *(float4*)&bv[4] = *(const float4*)(bias + n0 + 4);
#pragma unroll
        for (int r = 0; r < 8; r++) {
            int gr = x_row_of(m0 + r);
            size_t base = (size_t)gr * N + n0;
            float4 x0 = *(const float4*)(xres + base);
            float4 x1 = *(const float4*)(xres + base + 4);
            float o[8];
            o[0] = acc[r][0] + bv[0] + x0.x; o[1] = acc[r][1] + bv[1] + x0.y;
            o[2] = acc[r][2] + bv[2] + x0.z; o[3] = acc[r][3] + bv[3] + x0.w;
            o[4] = acc[r][4] + bv[4] + x1.x; o[5] = acc[r][5] + bv[5] + x1.y;
            o[6] = acc[r][6] + bv[6] + x1.z; o[7] = acc[r][7] + bv[7] + x1.w;
            *(float4*)(C + base)     = *(float4*)&o[0];
            *(float4*)(C + base + 4) = *(float4*)&o[4];
        }
    }
}

// ---------------- LayerNorm over d=192 (one warp per row, in place) --------
__global__ void k_ln(float* __restrict__ xd,
                     const float* __restrict__ g, const float* __restrict__ b)
{
    int gwarp = (blockIdx.x * blockDim.x + threadIdx.x) >> 5;
    int lane  = threadIdx.x & 31;
    if (gwarp >= MTOT) return;
    float* row = xd + (size_t)gwarp * DH;
    float v[6];
    float s = 0.0f;
#pragma unroll
    for (int i = 0; i < 6; i++) { v[i] = row[lane + 32 * i]; s += v[i]; }
#pragma unroll
    for (int o = 16; o; o >>= 1) s += __shfl_xor_sync(0xffffffffu, s, o);
    float mu = s * (1.0f / DH);
    float vs = 0.0f;
#pragma unroll
    for (int i = 0; i < 6; i++) { float d = v[i] - mu; vs += d * d; }
#pragma unroll
    for (int o = 16; o; o >>= 1) vs += __shfl_xor_sync(0xffffffffu, vs, o);
    float inv = rsqrtf(vs * (1.0f / DH) + 1e-5f);
#pragma unroll
    for (int i = 0; i < 6; i++) {
        int c = lane + 32 * i;
        row[c] = (v[i] - mu) * inv * g[c] + b[c];
    }
}

// ---------------- per-sequence retention attention -------------------------
__global__ void __launch_bounds__(256) k_attn(
    const float* __restrict__ Q, const float* __restrict__ Kmat,
    const float* __restrict__ V, float* __restrict__ R)
{
    __shared__ __align__(16) float sKV[SEQ][DH];
    const int q   = blockIdx.x;
    const int tid = threadIdx.x;
    const int n   = tid >> 3;
    const int j   = tid & 7;
    const size_t base = (size_t)q * SEQ * DH;

    for (int i = tid; i < SEQ * DH / 4; i += 256)
        ((float4*)&sKV[0][0])[i] = ((const float4*)(Kmat + base))[i];

    float qr[24];
    const float* qp = Q + base + (size_t)n * DH + j * 24;
#pragma unroll
    for (int dd = 0; dd < 6; dd++)
        *(float4*)&qr[dd * 4] = *(const float4*)(qp + dd * 4);
    __syncthreads();

    float att[SEQ];
#pragma unroll
    for (int m = 0; m < SEQ; m++) {
        float s = 0.0f;
#pragma unroll
        for (int dd = 0; dd < 6; dd++) {
            float4 kv = *(const float4*)&sKV[m][j * 24 + dd * 4];
            s += qr[dd*4+0]*kv.x + qr[dd*4+1]*kv.y + qr[dd*4+2]*kv.z + qr[dd*4+3]*kv.w;
        }
        att[m] = s;
    }
#pragma unroll
    for (int m = 0; m < SEQ; m++) {
#pragma unroll
        for (int o = 1; o < 8; o <<= 1)
            att[m] += __shfl_xor_sync(0xffffffffu, att[m], o);
        att[m] = (n >= m) ? ldexpf(att[m], m - n) : 0.0f;
    }

    __syncthreads();
    for (int i = tid; i < SEQ * DH / 4; i += 256)
        ((float4*)&sKV[0][0])[i] = ((const float4*)(V + base))[i];
    __syncthreads();

    float acc[24];
#pragma unroll
    for (int dd = 0; dd < 24; dd++) acc[dd] = 0.0f;
#pragma unroll
    for (int m = 0; m < SEQ; m++) {
        float a = att[m];
#pragma unroll
        for (int dd = 0; dd < 6; dd++) {
            float4 vv = *(const float4*)&sKV[m][j * 24 + dd * 4];
            acc[dd*4+0] += a * vv.x; acc[dd*4+1] += a * vv.y;
            acc[dd*4+2] += a * vv.z; acc[dd*4+3] += a * vv.w;
        }
    }
    float* rp = R + base + (size_t)n * DH + j * 24;
#pragma unroll
    for (int dd = 0; dd < 6; dd++)
        *(float4*)(rp + dd * 4) = *(const float4*)&acc[dd * 4];
}

// ---------------- launch --------------------------------------------------
extern "C" void kernel_launch(void* const* d_in, const int* in_sizes, int n_in,
                              void* d_out, int out_size)
{
    const float* x    = (const float*)d_in[0];
    const float* W1   = (const float*)d_in[1];
    const float* b1   = (const float*)d_in[2];
    const float* W2   = (const float*)d_in[3];
    const float* b2   = (const float*)d_in[4];
    const float* ln_g = (const float*)d_in[5];
    const float* ln_b = (const float*)d_in[6];
    const float* WQ   = (const float*)d_in[7];
    const float* WK   = (const float*)d_in[8];
    const float* WV   = (const float*)d_in[9];
    float* out = (float*)d_out;

    float* xd = nullptr; cudaGetSymbolAddress((void**)&xd, g_xd);
    float* qb = nullptr; cudaGetSymbolAddress((void**)&qb, g_q);
    float* kb = nullptr; cudaGetSymbolAddress((void**)&kb, g_k);
    float* vb = nullptr; cudaGetSymbolAddress((void**)&vb, g_v);
    float* rb = nullptr; cudaGetSymbolAddress((void**)&rb, g_ret);

    k_tables<<<12, 256>>>();

    // GEMM1: x(gathered) @ W1 + b1 -> g_xd   [M=50176, K=768, N=192]
    k_gemm<0, 64><<<dim3(DH / 64, MTOT / 128), 128>>>(x, W1, b1, nullptr, xd, DD, DH);
    k_ln<<<MTOT / 8, 256>>>(xd, ln_g, ln_b);
    // QKV: h @ W{Q,K,V}  [M=50176, K=192, N=192]
    k_gemm<1, 64><<<dim3(DH / 64, MTOT / 128), 128>>>(xd, WQ, nullptr, nullptr, qb, DH, DH);
    k_gemm<2, 64><<<dim3(DH / 64, MTOT / 128), 128>>>(xd, WK, nullptr, nullptr, kb, DH, DH);
    k_gemm<3, 64><<<dim3(DH / 64, MTOT / 128), 128>>>(xd, WV, nullptr, nullptr, vb, DH, DH);
    k_attn<<<NSEQ, 256>>>(qb, kb, vb, rb);
    // GEMM2: ret @ W2 + b2 + x (residual) -> d_out  [M=50176, K=192, N=768]
    k_gemm<4, 128><<<dim3(DD / 128, MTOT / 128), 256>>>(rb, W2, b2, x, out, DH, DD);
}

// round 5
// speedup vs baseline: 1.0205x; 1.0205x over previous
#include <cuda_runtime.h>
#include <cstdint>

// ---------------- problem constants ----------------
#define HW   196
#define BB   8
#define SEQ  32
#define DD   768
#define DH   192
#define HALF 96                  // DH/2
#define NSEQ (BB*HW)             // 1568
#define MTOT (NSEQ*SEQ)          // 50176

// ---------------- scratch (__device__ globals) ------------------------------
__device__ float g_xd [MTOT*DH];
__device__ float g_q  [MTOT*DH];
__device__ float g_k  [MTOT*DH];
__device__ float g_v  [MTOT*DH];
__device__ float g_ret[MTOT*DH];

// xPos tables: [t (0..31)][p (0..95)]
__device__ float g_cos_u[SEQ*HALF];
__device__ float g_sin_u[SEQ*HALF];
__device__ float g_cos_d[SEQ*HALF];
__device__ float g_sin_d[SEQ*HALF];

// row m of the logical xr[(b*hw), s, D] maps to this row of x[(hw), b*s, D]
__device__ __forceinline__ int x_row_of(int m) {
    int q  = m >> 5;
    int t  = m & 31;
    int bi = q / HW;
    int hi = q - bi * HW;
    return hi * (BB * SEQ) + bi * SEQ + t;
}

// ---------------- packed f32x2 helpers (sm_100-family PTX) ------------------
__device__ __forceinline__ uint64_t pack_dup(float x) {
    uint64_t r;
    asm("mov.b64 %0, {%1, %1};" : "=l"(r) : "f"(x));
    return r;
}
__device__ __forceinline__ void fma2(uint64_t& d, uint64_t a, uint64_t b) {
    asm("fma.rn.f32x2 %0, %1, %2, %0;" : "+l"(d) : "l"(a), "l"(b));
}
__device__ __forceinline__ float2 unpack2(uint64_t v) {
    float2 f;
    asm("mov.b64 {%0, %1}, %2;" : "=f"(f.x), "=f"(f.y) : "l"(v));
    return f;
}

// ---------------- xPos table precompute (fp64) ------------------------------
__global__ void k_tables() {
    int i = blockIdx.x * blockDim.x + threadIdx.x;
    if (i >= SEQ * HALF) return;
    int t = i / HALF, p = i % HALF;
    double base = (2.0 * p + 0.4 * (double)DH) / (1.4 * (double)DH);
    double sc_u = pow(base, (double)t / 512.0);
    double sc_d = 1.0 / sc_u;
    double invf = pow(10000.0, -(double)p / (double)HALF);
    double ang  = (double)t * invf;
    double s = sin(ang), c = cos(ang);
    g_cos_u[i] = (float)(c * sc_u);
    g_sin_u[i] = (float)(s * sc_u);
    g_cos_d[i] = (float)(c * sc_d);
    g_sin_d[i] = (float)(s * sc_d);
}

// ---------------- tiled SGEMM with packed f32x2 FMAs ------------------------
// BM=128, BK=16, microtile 8x8 (acc packed as 8x4 f32x2), double-buffered smem.
// MODE 0: A gathered from x, +bias           -> C
// MODE 1: xPos upscale epilogue              -> C
// MODE 2: xPos downscale epilogue            -> C
// MODE 3: plain                              -> C
// MODE 4: +bias +x residual (gathered), gathered store -> C
template <int MODE, int BN>
__global__ void __launch_bounds__((BN/8)*16) k_gemm(
    const float* __restrict__ A, const float* __restrict__ B,
    const float* __restrict__ bias, const float* __restrict__ xres,
    float* __restrict__ C, int K, int N)
{
    constexpr int BM = 128, BK = 16;
    constexpr int THREADS  = (BN / 8) * 16;
    constexpr int AMP      = 132;
    constexpr int A_F4_PER = (BM * BK / 4) / THREADS;   // 4 (BN=64) or 2 (BN=128)
    constexpr int B_F4_PER = (BK * BN / 4) / THREADS;   // 2

    __shared__ __align__(16) float As[2][BK][AMP];
    __shared__ __align__(16) float Bs[2][BK][BN];

    const int tid = threadIdx.x;
    const int txx = tid % (BN / 8);
    const int tyy = tid / (BN / 8);
    const int bm  = blockIdx.y * BM;
    const int bn  = blockIdx.x * BN;

    int aRow[A_F4_PER], aKq[A_F4_PER];
    const float* aPtr[A_F4_PER];
#pragma unroll
    for (int i = 0; i < A_F4_PER; i++) {
        int f4 = tid + i * THREADS;
        aRow[i] = f4 >> 2;
        aKq[i]  = f4 & 3;
        int gm  = bm + aRow[i];
        int gr  = (MODE == 0) ? x_row_of(gm) : gm;
        aPtr[i] = A + (size_t)gr * K + aKq[i] * 4;
    }
    int bRow[B_F4_PER], bCol[B_F4_PER];
#pragma unroll
    for (int i = 0; i < B_F4_PER; i++) {
        int f4 = tid + i * THREADS;
        bRow[i] = f4 / (BN / 4);
        bCol[i] = (f4 % (BN / 4)) * 4;
    }

    // packed accumulators: acc2[r][cp] holds columns {2cp, 2cp+1} of row r
    uint64_t acc2[8][4];
#pragma unroll
    for (int r = 0; r < 8; r++)
#pragma unroll
        for (int cp = 0; cp < 4; cp++) acc2[r][cp] = 0ull;

    float4 aReg[A_F4_PER], bReg[B_F4_PER];

    auto loadG = [&](int k0) {
#pragma unroll
        for (int i = 0; i < A_F4_PER; i++)
            aReg[i] = *(const float4*)(aPtr[i] + k0);
#pragma unroll
        for (int i = 0; i < B_F4_PER; i++)
            bReg[i] = *(const float4*)(B + (size_t)(k0 + bRow[i]) * N + bn + bCol[i]);
    };
    auto storeS = [&](int buf) {
#pragma unroll
        for (int i = 0; i < A_F4_PER; i++) {
            As[buf][aKq[i] * 4 + 0][aRow[i]] = aReg[i].x;
            As[buf][aKq[i] * 4 + 1][aRow[i]] = aReg[i].y;
            As[buf][aKq[i] * 4 + 2][aRow[i]] = aReg[i].z;
            As[buf][aKq[i] * 4 + 3][aRow[i]] = aReg[i].w;
        }
#pragma unroll
        for (int i = 0; i < B_F4_PER; i++)
            *(float4*)&Bs[buf][bRow[i]][bCol[i]] = bReg[i];
    };
    auto compute = [&](int buf) {
#pragma unroll
        for (int kk = 0; kk < BK; kk++) {
            float a[8];
            *(float4*)&a[0] = *(const float4*)&As[buf][kk][tyy * 8];
            *(float4*)&a[4] = *(const float4*)&As[buf][kk][tyy * 8 + 4];
            uint64_t b2[4];
            const uint64_t* bp = (const uint64_t*)&Bs[buf][kk][txx * 8];
            b2[0] = bp[0]; b2[1] = bp[1]; b2[2] = bp[2]; b2[3] = bp[3];
            uint64_t a2[8];
#pragma unroll
            for (int r = 0; r < 8; r++) a2[r] = pack_dup(a[r]);
#pragma unroll
            for (int r = 0; r < 8; r++)
#pragma unroll
                for (int cp = 0; cp < 4; cp++)
                    fma2(acc2[r][cp], a2[r], b2[cp]);
        }
    };

    loadG(0);
    storeS(0);
    __syncthreads();
    int cur = 0;
    for (int k0 = BK; k0 < K; k0 += BK) {
        loadG(k0);
        compute(cur);
        storeS(cur ^ 1);
        __syncthreads();
        cur ^= 1;
    }
    compute(cur);

    // unpack to plain fp32 accumulator tile
    float acc[8][8];
#pragma unroll
    for (int r = 0; r < 8; r++)
#pragma unroll
        for (int cp = 0; cp < 4; cp++) {
            float2 t = unpack2(acc2[r][cp]);
            acc[r][2 * cp]     = t.x;
            acc[r][2 * cp + 1] = t.y;
        }

    const int m0 = bm + tyy * 8;
    const int n0 = bn + txx * 8;

    if (MODE == 0) {
        float bv[8];
        *(float4*)&bv[0] = *(const float4*)(bias + n0);
        *(float4*)&bv[4] = *(const float4*)(bias + n0 + 4);
#pragma unroll
        for (int r = 0; r < 8; r++) {
            float o[8];
#pragma unroll
            for (int c = 0; c < 8; c++) o[c] = acc[r][c] + bv[c];
            *(float4*)(C + (size_t)(m0 + r) * N + n0)     = *(float4*)&o[0];
            *(float4*)(C + (size_t)(m0 + r) * N + n0 + 4) = *(float4*)&o[4];
        }
    } else if (MODE == 1 || MODE == 2) {
        const float* ct = (MODE == 1) ? g_cos_u : g_cos_d;
        const float* st = (MODE == 1) ? g_sin_u : g_sin_d;
        const int p0 = n0 >> 1;
#pragma unroll
        for (int r = 0; r < 8; r++) {
            int m = m0 + r;
            int t = m & 31;
            float o[8];
#pragma unroll
            for (int pp = 0; pp < 4; pp++) {
                float cc = ct[t * HALF + p0 + pp];
                float ss = st[t * HALF + p0 + pp];
                float e = acc[r][pp * 2], od = acc[r][pp * 2 + 1];
                o[pp * 2]     = e * cc - od * ss;
                o[pp * 2 + 1] = od * cc + e * ss;
            }
            *(float4*)(C + (size_t)m * N + n0)     = *(float4*)&o[0];
            *(float4*)(C + (size_t)m * N + n0 + 4) = *(float4*)&o[4];
        }
    } else if (MODE == 3) {
#pragma unroll
        for (int r = 0; r < 8; r++) {
            *(float4*)(C + (size_t)(m0 + r) * N + n0)     = *(float4*)&acc[r][0];
            *(float4*)(C + (size_t)(m0 + r) * N + n0 + 4) = *(float4*)&acc[r][4];
        }
    } else { // MODE 4
        float bv[8];
        *(float4*)&bv[0] = *(const float4*)(bias + n0);
        *(float4*)&bv[4] = *(const float4*)(bias + n0 + 4);
#pragma unroll
        for (int r = 0; r < 8; r++) {
            int gr = x_row_of(m0 + r);
            size_t base = (size_t)gr * N + n0;
            float4 x0 = *(const float4*)(xres + base);
            float4 x1 = *(const float4*)(xres + base + 4);
            float o[8];
            o[0] = acc[r][0] + bv[0] + x0.x; o[1] = acc[r][1] + bv[1] + x0.y;
            o[2] = acc[r][2] + bv[2] + x0.z; o[3] = acc[r][3] + bv[3] + x0.w;
            o[4] = acc[r][4] + bv[4] + x1.x; o[5] = acc[r][5] + bv[5] + x1.y;
            o[6] = acc[r][6] + bv[6] + x1.z; o[7] = acc[r][7] + bv[7] + x1.w;
            *(float4*)(C + base)     = *(float4*)&o[0];
            *(float4*)(C + base + 4) = *(float4*)&o[4];
        }
    }
}

// ---------------- LayerNorm over d=192 (one warp per row, in place) --------
__global__ void k_ln(float* __restrict__ xd,
                     const float* __restrict__ g, const float* __restrict__ b)
{
    int gwarp = (blockIdx.x * blockDim.x + threadIdx.x) >> 5;
    int lane  = threadIdx.x & 31;
    if (gwarp >= MTOT) return;
    float* row = xd + (size_t)gwarp * DH;
    float v[6];
    float s = 0.0f;
#pragma unroll
    for (int i = 0; i < 6; i++) { v[i] = row[lane + 32 * i]; s += v[i]; }
#pragma unroll
    for (int o = 16; o; o >>= 1) s += __shfl_xor_sync(0xffffffffu, s, o);
    float mu = s * (1.0f / DH);
    float vs = 0.0f;
#pragma unroll
    for (int i = 0; i < 6; i++) { float d = v[i] - mu; vs += d * d; }
#pragma unroll
    for (int o = 16; o; o >>= 1) vs += __shfl_xor_sync(0xffffffffu, vs, o);
    float inv = rsqrtf(vs * (1.0f / DH) + 1e-5f);
#pragma unroll
    for (int i = 0; i < 6; i++) {
        int c = lane + 32 * i;
        row[c] = (v[i] - mu) * inv * g[c] + b[c];
    }
}

// ---------------- per-sequence retention attention -------------------------
__global__ void __launch_bounds__(256) k_attn(
    const float* __restrict__ Q, const float* __restrict__ Kmat,
    const float* __restrict__ V, float* __restrict__ R)
{
    __shared__ __align__(16) float sKV[SEQ][DH];
    const int q   = blockIdx.x;
    const int tid = threadIdx.x;
    const int n   = tid >> 3;
    const int j   = tid & 7;
    const size_t base = (size_t)q * SEQ * DH;

    for (int i = tid; i < SEQ * DH / 4; i += 256)
        ((float4*)&sKV[0][0])[i] = ((const float4*)(Kmat + base))[i];

    float qr[24];
    const float* qp = Q + base + (size_t)n * DH + j * 24;
#pragma unroll
    for (int dd = 0; dd < 6; dd++)
        *(float4*)&qr[dd * 4] = *(const float4*)(qp + dd * 4);
    __syncthreads();

    float att[SEQ];
#pragma unroll
    for (int m = 0; m < SEQ; m++) {
        float s = 0.0f;
#pragma unroll
        for (int dd = 0; dd < 6; dd++) {
            float4 kv = *(const float4*)&sKV[m][j * 24 + dd * 4];
            s += qr[dd*4+0]*kv.x + qr[dd*4+1]*kv.y + qr[dd*4+2]*kv.z + qr[dd*4+3]*kv.w;
        }
        att[m] = s;
    }
#pragma unroll
    for (int m = 0; m < SEQ; m++) {
#pragma unroll
        for (int o = 1; o < 8; o <<= 1)
            att[m] += __shfl_xor_sync(0xffffffffu, att[m], o);
        att[m] = (n >= m) ? ldexpf(att[m], m - n) : 0.0f;
    }

    __syncthreads();
    for (int i = tid; i < SEQ * DH / 4; i += 256)
        ((float4*)&sKV[0][0])[i] = ((const float4*)(V + base))[i];
    __syncthreads();

    float acc[24];
#pragma unroll
    for (int dd = 0; dd < 24; dd++) acc[dd] = 0.0f;
#pragma unroll
    for (int m = 0; m < SEQ; m++) {
        float a = att[m];
#pragma unroll
        for (int dd = 0; dd < 6; dd++) {
            float4 vv = *(const float4*)&sKV[m][j * 24 + dd * 4];
            acc[dd*4+0] += a * vv.x; acc[dd*4+1] += a * vv.y;
            acc[dd*4+2] += a * vv.z; acc[dd*4+3] += a * vv.w;
        }
    }
    float* rp = R + base + (size_t)n * DH + j * 24;
#pragma unroll
    for (int dd = 0; dd < 6; dd++)
        *(float4*)(rp + dd * 4) = *(const float4*)&acc[dd * 4];
}

// ---------------- launch --------------------------------------------------
extern "C" void kernel_launch(void* const* d_in, const int* in_sizes, int n_in,
                              void* d_out, int out_size)
{
    const float* x    = (const float*)d_in[0];
    const float* W1   = (const float*)d_in[1];
    const float* b1   = (const float*)d_in[2];
    const float* W2   = (const float*)d_in[3];
    const float* b2   = (const float*)d_in[4];
    const float* ln_g = (const float*)d_in[5];
    const float* ln_b = (const float*)d_in[6];
    const float* WQ   = (const float*)d_in[7];
    const float* WK   = (const float*)d_in[8];
    const float* WV   = (const float*)d_in[9];
    float* out = (float*)d_out;

    float* xd = nullptr; cudaGetSymbolAddress((void**)&xd, g_xd);
    float* qb = nullptr; cudaGetSymbolAddress((void**)&qb, g_q);
    float* kb = nullptr; cudaGetSymbolAddress((void**)&kb, g_k);
    float* vb = nullptr; cudaGetSymbolAddress((void**)&vb, g_v);
    float* rb = nullptr; cudaGetSymbolAddress((void**)&rb, g_ret);

    k_tables<<<12, 256>>>();

    // GEMM1: x(gathered) @ W1 + b1 -> g_xd   [M=50176, K=768, N=192]
    k_gemm<0, 64><<<dim3(DH / 64, MTOT / 128), 128>>>(x, W1, b1, nullptr, xd, DD, DH);
    k_ln<<<MTOT / 8, 256>>>(xd, ln_g, ln_b);
    // QKV: h @ W{Q,K,V}  [M=50176, K=192, N=192]
    k_gemm<1, 64><<<dim3(DH / 64, MTOT / 128), 128>>>(xd, WQ, nullptr, nullptr, qb, DH, DH);
    k_gemm<2, 64><<<dim3(DH / 64, MTOT / 128), 128>>>(xd, WK, nullptr, nullptr, kb, DH, DH);
    k_gemm<3, 64><<<dim3(DH / 64, MTOT / 128), 128>>>(xd, WV, nullptr, nullptr, vb, DH, DH);
    k_attn<<<NSEQ, 256>>>(qb, kb, vb, rb);
    // GEMM2: ret @ W2 + b2 + x (residual) -> d_out  [M=50176, K=192, N=768]
    k_gemm<4, 128><<<dim3(DD / 128, MTOT / 128), 256>>>(rb, W2, b2, x, out, DH, DD);
}